// round 17
// baseline (speedup 1.0000x reference)
#include <cuda_runtime.h>
#include <cstdint>

// B=8, C=4, H=W=1024, PATCH=16, DOWN=4 -> L=4096 (64x64 patches), M=256.
// att_gt[b,c,l,m] = (1/4096) * sum_{k: class(b,l,k)==c} cnt[b,c, pix(m,k)]
//   cnt in [0,16]. Loss = mean((att - att_gt)^2) over 33.5M elements.
// target is int32 on disk. Scalar smem path, u8 V table, LDS.128 2-k pairing.

// ---------------- device scratch ----------------
static __device__ __align__(16) uint8_t g_T[8u * 4096u * 256u];      // [b][l][k] class
static __device__ __align__(16) uint8_t g_V[8u * 4u * 256u * 256u];  // [b][c][k][m] u8
static __device__ __align__(16) uint8_t g_list[8u * 4096u * 256u];   // [b][l] k's by class
static __device__ ushort4  g_cnt[8u * 4096u];
static __device__ double   g_part[256];

// ---------------- kernel 1: target -> class bytes g_T[b][l][k] ----------
__global__ void k_compact(const int* __restrict__ tgt) {
    int t = threadIdx.x;
    int py = blockIdx.x & 63, b = blockIdx.x >> 6;
#pragma unroll 4
    for (int ky = 0; ky < 16; ky++) {
        int4 q = *reinterpret_cast<const int4*>(
            tgt + ((size_t)b << 20) + (size_t)(py * 16 + ky) * 1024 + t * 4);
        uint32_t w = (uint32_t)(q.x & 255) | ((uint32_t)(q.y & 255) << 8)
                   | ((uint32_t)(q.z & 255) << 16) | ((uint32_t)(q.w & 255) << 24);
        size_t off = ((size_t)b * 4096 + py * 64 + (t >> 2)) * 256
                   + ky * 16 + (t & 3) * 4;
        *reinterpret_cast<uint32_t*>(g_T + off) = w;
    }
}

// ---------------- kernel 2: pooled counts -> g_V u8 [b][c][k][m] --------
__global__ void k_pool() {
    __shared__ __align__(16) uint8_t stage[4][16][16];   // [c][kx][mx]
    int X = threadIdx.x;
    int Y = blockIdx.x & 255, b = blockIdx.x >> 8;
    int py = Y >> 2, a = Y & 3, px = X >> 2, bb = X & 3;
    const uint8_t* row = g_T + ((size_t)(b * 4096 + py * 64 + px) << 8);
    uint32_t w0 = *(const uint32_t*)(row + (4 * a + 0) * 16 + 4 * bb);
    uint32_t w1 = *(const uint32_t*)(row + (4 * a + 1) * 16 + 4 * bb);
    uint32_t w2 = *(const uint32_t*)(row + (4 * a + 2) * 16 + 4 * bb);
    uint32_t w3 = *(const uint32_t*)(row + (4 * a + 3) * 16 + 4 * bb);
    int kx = X & 15, mx = X >> 4;
#pragma unroll
    for (int c = 0; c < 4; c++) {
        uint32_t cc = 0x01010101u * (uint32_t)c;
        int s = __dp4a((int)(__vcmpeq4(w0, cc) & 0x01010101u), 0x01010101, 0);
        s = __dp4a((int)(__vcmpeq4(w1, cc) & 0x01010101u), 0x01010101, s);
        s = __dp4a((int)(__vcmpeq4(w2, cc) & 0x01010101u), 0x01010101, s);
        s = __dp4a((int)(__vcmpeq4(w3, cc) & 0x01010101u), 0x01010101, s);
        stage[c][kx][mx] = (uint8_t)s;
    }
    __syncthreads();
    if (X < 64) {
        int c = X >> 4, kxe = X & 15;
        int kk = (Y & 15) * 16 + kxe;
        int mbase = (Y >> 4) << 4;
        size_t bc = (size_t)b * 4 + c;
        uint4 v = *reinterpret_cast<const uint4*>(&stage[c][kxe][0]);
        *reinterpret_cast<uint4*>(g_V + (bc << 16) + (size_t)kk * 256 + mbase) = v;
    }
}

// ---------------- kernel 3: per-(b,l) counting sort of k by class -------
__global__ void k_lists() {
    __shared__ uint8_t sc[8 * 256];
    int warp = threadIdx.x >> 5, lane = threadIdx.x & 31;
    int gw = blockIdx.x * 8 + warp;                  // b*4096 + l
    ((uint64_t*)(sc + warp * 256))[lane] =
        ((const uint64_t*)(g_T + ((size_t)gw << 8)))[lane];
    __syncwarp();
    const uint8_t* cw = sc + warp * 256;
    int t0 = 0, t1 = 0, t2 = 0, t3 = 0;
#pragma unroll
    for (int r = 0; r < 8; r++) {
        int c = cw[r * 32 + lane];
        t0 += __popc(__ballot_sync(0xffffffffu, c == 0));
        t1 += __popc(__ballot_sync(0xffffffffu, c == 1));
        t2 += __popc(__ballot_sync(0xffffffffu, c == 2));
        t3 += __popc(__ballot_sync(0xffffffffu, c == 3));
    }
    int b0 = 0, b1 = t0, b2 = t0 + t1, b3 = t0 + t1 + t2;
    uint8_t* out = g_list + ((size_t)gw << 8);
    unsigned lt = (1u << lane) - 1u;
#pragma unroll
    for (int r = 0; r < 8; r++) {
        int k = r * 32 + lane;
        int c = cw[k];
        unsigned m0 = __ballot_sync(0xffffffffu, c == 0);
        unsigned m1 = __ballot_sync(0xffffffffu, c == 1);
        unsigned m2 = __ballot_sync(0xffffffffu, c == 2);
        unsigned m3 = __ballot_sync(0xffffffffu, c == 3);
        int pos = (c == 0) ? b0 + __popc(m0 & lt)
                : (c == 1) ? b1 + __popc(m1 & lt)
                : (c == 2) ? b2 + __popc(m2 & lt)
                :            b3 + __popc(m3 & lt);
        out[pos] = (uint8_t)k;
        b0 += __popc(m0); b1 += __popc(m1); b2 += __popc(m2); b3 += __popc(m3);
    }
    if (lane == 0)
        g_cnt[gw] = make_ushort4((unsigned short)t0, (unsigned short)t1,
                                 (unsigned short)t2, (unsigned short)t3);
}

// ---------------- kernel 4: main accumulation + fused MSE ----------------
// grid (lg=8, c=4, b=8) = 256 blocks, 512 threads (16 warps), occ 2.
// smem: u8 V slab 64KB + 16x256B lists. Warp owns one l per iter.
// LDS.128 2-k pairing: half-warp h serves k_h; lane-in-half lh covers
// m = lh*16..+15 as 4 u32 byte windows (8 adds/window per 16-k chunk).
// Cross-half combine via shfl_xor(16) on u16x2 accumulators.
#define FLUSH16()                                                         \
    do {                                                                  \
        acc0 += __byte_perm(w0, 0, 0x4140); acc1 += __byte_perm(w0, 0, 0x4342); \
        acc2 += __byte_perm(w1, 0, 0x4140); acc3 += __byte_perm(w1, 0, 0x4342); \
        acc4 += __byte_perm(w2, 0, 0x4140); acc5 += __byte_perm(w2, 0, 0x4342); \
        acc6 += __byte_perm(w3, 0, 0x4140); acc7 += __byte_perm(w3, 0, 0x4342); \
        w0 = w1 = w2 = w3 = 0;                                            \
    } while (0)

__global__ void __launch_bounds__(512, 2) k_main(const float* __restrict__ att) {
    extern __shared__ uint8_t sm[];
    uint8_t* Vs = sm;                        // 65536 B
    uint8_t* Ls = sm + 65536;                // 16 warps * 256 B
    double*  wsum = (double*)(sm + 65536 + 4096);
    int b = blockIdx.z, c = blockIdx.y, lg = blockIdx.x;
    size_t bc = (size_t)b * 4 + c;

    {   // load V slab (coalesced uint4)
        const uint4* src = (const uint4*)(g_V + (bc << 16));
        uint4* dst = (uint4*)Vs;
        for (int i = threadIdx.x; i < 4096; i += 512) dst[i] = src[i];
    }
    __syncthreads();

    int warp = threadIdx.x >> 5, lane = threadIdx.x & 31;
    int h = lane >> 4, lh = lane & 15;
    uint32_t gate = h ? 0u : 0xFFFFFFFFu;
    uint32_t selA = 0x4440u | (uint32_t)h;        // byte 0+h of idx word
    uint32_t selB = 0x4440u | (uint32_t)(2 + h);  // byte 2+h
    uint8_t* lw = Ls + warp * 256;
    const uint8_t* Vbl = Vs + (lh << 4);
    const float inv = 1.0f / 4096.0f;
    float s = 0.0f;

    for (int li = 0; li < 32; li++) {
        int l = (lg << 9) + (li << 4) + warp;
        size_t lbase = (size_t)b * 4096 + l;
        __syncwarp();
        ((uint64_t*)lw)[lane] = ((const uint64_t*)g_list)[lbase * 32 + lane];
        __syncwarp();
        ushort4 cn = g_cnt[lbase];
        int start = (c > 0 ? (int)cn.x : 0) + (c > 1 ? (int)cn.y : 0)
                  + (c > 2 ? (int)cn.z : 0);
        int n = (c == 0) ? (int)cn.x : (c == 1) ? (int)cn.y
              : (c == 2) ? (int)cn.z : (int)cn.w;

        const float4* ap = (const float4*)att + ((bc * 4096 + l) << 6);
        uint32_t acc0 = 0, acc1 = 0, acc2 = 0, acc3 = 0;
        uint32_t acc4 = 0, acc5 = 0, acc6 = 0, acc7 = 0;
        uint32_t w0 = 0, w1 = 0, w2 = 0, w3 = 0;
        int p = start, e = start + n;

        // scalar gated head to 4-alignment (<=3 adds)
        while ((p & 3) && p < e) {
            uint32_t k = lw[p++];
            uint4 r = *(const uint4*)(Vbl + (k << 8));
            w0 += r.x & gate; w1 += r.y & gate;
            w2 += r.z & gate; w3 += r.w & gate;
        }
        FLUSH16();
        const uint32_t* wp = (const uint32_t*)lw;

        // 16-k chunks: 4 idx words x 2 paired LDS.128 steps
        while (e - p >= 16) {
#pragma unroll
            for (int g = 0; g < 4; g++) {
                uint32_t i4 = wp[(p >> 2) + g];
                uint32_t kA = __byte_perm(i4, 0, selA);
                uint4 rA = *(const uint4*)(Vbl + (kA << 8));
                w0 += rA.x; w1 += rA.y; w2 += rA.z; w3 += rA.w;
                uint32_t kB = __byte_perm(i4, 0, selB);
                uint4 rB = *(const uint4*)(Vbl + (kB << 8));
                w0 += rB.x; w1 += rB.y; w2 += rB.z; w3 += rB.w;
            }
            FLUSH16();
            p += 16;
        }
        // tail (<16 k): paired steps, then <=1 scalar gated
        while (e - p >= 2) {
            uint32_t i4 = wp[p >> 2];
            uint32_t sel = (0x4440u | (uint32_t)((p & 3) + h));
            uint32_t k = __byte_perm(i4, 0, sel);
            uint4 r = *(const uint4*)(Vbl + (k << 8));
            w0 += r.x; w1 += r.y; w2 += r.z; w3 += r.w;
            p += 2;
        }
        if (p < e) {
            uint32_t k = lw[p];
            uint4 r = *(const uint4*)(Vbl + (k << 8));
            w0 += r.x & gate; w1 += r.y & gate;
            w2 += r.z & gate; w3 += r.w & gate;
        }
        FLUSH16();

        // combine halves (u16x2 adds, each lane sum <= 4096: carry-safe)
        acc0 += __shfl_xor_sync(0xffffffffu, acc0, 16);
        acc1 += __shfl_xor_sync(0xffffffffu, acc1, 16);
        acc2 += __shfl_xor_sync(0xffffffffu, acc2, 16);
        acc3 += __shfl_xor_sync(0xffffffffu, acc3, 16);
        acc4 += __shfl_xor_sync(0xffffffffu, acc4, 16);
        acc5 += __shfl_xor_sync(0xffffffffu, acc5, 16);
        acc6 += __shfl_xor_sync(0xffffffffu, acc6, 16);
        acc7 += __shfl_xor_sync(0xffffffffu, acc7, 16);

        // fused MSE: half h covers m = lh*16 + h*8 .. +7  (accs 4h..4h+3)
        uint32_t e0, e1, e2, e3;
        if (h == 0) { e0 = acc0; e1 = acc1; e2 = acc2; e3 = acc3; }
        else        { e0 = acc4; e1 = acc5; e2 = acc6; e3 = acc7; }
        int mbase = (lh << 4) + (h << 3);
        float4 q0 = __ldg(ap + (mbase >> 2));
        float4 q1 = __ldg(ap + (mbase >> 2) + 1);
        float d;
        d = q0.x - (float)(e0 & 0xffffu) * inv; s += d * d;
        d = q0.y - (float)(e0 >> 16)     * inv; s += d * d;
        d = q0.z - (float)(e1 & 0xffffu) * inv; s += d * d;
        d = q0.w - (float)(e1 >> 16)     * inv; s += d * d;
        d = q1.x - (float)(e2 & 0xffffu) * inv; s += d * d;
        d = q1.y - (float)(e2 >> 16)     * inv; s += d * d;
        d = q1.z - (float)(e3 & 0xffffu) * inv; s += d * d;
        d = q1.w - (float)(e3 >> 16)     * inv; s += d * d;
    }

    // deterministic block reduction
#pragma unroll
    for (int o = 16; o > 0; o >>= 1) s += __shfl_down_sync(0xffffffffu, s, o);
    if (lane == 0) wsum[warp] = (double)s;
    __syncthreads();
    if (threadIdx.x == 0) {
        double t = 0.0;
#pragma unroll
        for (int w = 0; w < 16; w++) t += wsum[w];
        g_part[((size_t)blockIdx.z * 4 + blockIdx.y) * 8 + blockIdx.x] = t;
    }
}

// ---------------- kernel 5: final deterministic reduction ----------------
__global__ void k_final(float* __restrict__ out) {
    __shared__ double sh[256];
    int t = threadIdx.x;
    sh[t] = g_part[t];
    __syncthreads();
#pragma unroll
    for (int o = 128; o > 0; o >>= 1) {
        if (t < o) sh[t] += sh[t + o];
        __syncthreads();
    }
    if (t == 0) out[0] = (float)(sh[0] / 33554432.0);
}

// ---------------- launch -------------------------------------------------
extern "C" void kernel_launch(void* const* d_in, const int* in_sizes, int n_in,
                              void* d_out, int out_size) {
    (void)in_sizes; (void)n_in; (void)out_size;
    // d_in[0] = pred (unused), d_in[1] = target int32, d_in[2] = attentions f32
    const int*   tgt = (const int*)d_in[1];
    const float* att = (const float*)d_in[2];
    float*       out = (float*)d_out;

    const int MAIN_SMEM = 65536 + 4096 + 16 * (int)sizeof(double);
    cudaFuncSetAttribute(k_main, cudaFuncAttributeMaxDynamicSharedMemorySize,
                         MAIN_SMEM);

    // k_main at launch position 3 -> ncu capture slot
    k_compact<<<512, 256>>>(tgt);
    k_pool<<<2048, 256>>>();
    k_lists<<<4096, 256>>>();
    k_main<<<dim3(8, 4, 8), 512, MAIN_SMEM>>>(att);
    k_final<<<1, 256>>>(out);
}